// round 2
// baseline (speedup 1.0000x reference)
#include <cuda_runtime.h>
#include <math.h>

#define T_STEPS 400
#define BATCH   128
#define HID     512
#define OC      64

typedef unsigned long long ull;

__device__ float g_ybuf[OC * T_STEPS * BATCH];   // [oc][t][b]
__device__ float g_seq [T_STEPS * OC * BATCH];   // [t][c][b]
__device__ float g_scale[OC];
__device__ float g_shift[OC];
__device__ float g_memL[2][OC * BATCH];
__device__ float g_mem1[2][HID * BATCH];
__device__ float g_syn1[HID * BATCH];
__device__ float g_spk1[HID * BATCH];
__device__ float g_mem2[2][HID * BATCH];
__device__ float g_syn2[HID * BATCH];
__device__ float g_acc2[HID * BATCH];

__device__ __forceinline__ float sigf(float x) { return 1.f / (1.f + expf(-x)); }

__device__ __forceinline__ ull packf2(float w) {
    ull r; unsigned u = __float_as_uint(w);
    asm("mov.b64 %0, {%1, %1};" : "=l"(r) : "r"(u));
    return r;
}
__device__ __forceinline__ void fma2(ull& acc, ull a, ull b) {
    asm("fma.rn.f32x2 %0, %1, %2, %0;" : "+l"(acc) : "l"(a), "l"(b));
}

__device__ __forceinline__ void gemm64(const float* __restrict__ s_state,
                                       const float* __restrict__ s_w,
                                       int g, int bbase, ull acc[4]) {
    const float* wr = s_w + g * 65;
#pragma unroll 8
    for (int kk = 0; kk < 64; kk++) {
        ull wp = packf2(wr[kk]);
        const ull* sp = (const ull*)(s_state + kk * 128 + bbase);
        fma2(acc[0], sp[0], wp);
        fma2(acc[1], sp[1], wp);
        fma2(acc[2], sp[2], wp);
        fma2(acc[3], sp[3], wp);
    }
}

__global__ void init_kernel() {
    int i = blockIdx.x * 256 + threadIdx.x;          // grid covers 131072
    if (i < 2 * OC * BATCH) ((float*)g_memL)[i] = 0.f;
    if (i < 2 * HID * BATCH) { ((float*)g_mem1)[i] = 0.f; ((float*)g_mem2)[i] = 0.f; }
    if (i < HID * BATCH) { g_syn1[i] = 0.f; g_spk1[i] = 0.f; g_syn2[i] = 0.f; g_acc2[i] = 0.f; }
}

// conv1d over time (pad=2, k=5). block = t (400), threads = b (128)
__global__ void conv_kernel(const float* __restrict__ x, const float* __restrict__ w) {
    __shared__ float s_w[OC * 70];
    int t = blockIdx.x, b = threadIdx.x;
    for (int i = b; i < OC * 70; i += 128) s_w[i] = w[i];
    float xr[5][14];
#pragma unroll
    for (int k = 0; k < 5; k++) {
        int tt = t + k - 2;
        bool ok = (tt >= 0 && tt < T_STEPS);
#pragma unroll
        for (int c = 0; c < 14; c++)
            xr[k][c] = ok ? x[(tt * BATCH + b) * 14 + c] : 0.f;
    }
    __syncthreads();
    for (int oc = 0; oc < OC; oc++) {
        float acc = 0.f;
        const float* wr = s_w + oc * 70;
#pragma unroll
        for (int c = 0; c < 14; c++)
#pragma unroll
            for (int k = 0; k < 5; k++)
                acc = fmaf(xr[k][c], wr[c * 5 + k], acc);
        g_ybuf[oc * (T_STEPS * BATCH) + t * BATCH + b] = acc;
    }
}

__global__ void stats_kernel(const float* __restrict__ bn_g, const float* __restrict__ bn_b) {
    int c = blockIdx.x;
    const float* base = g_ybuf + c * (T_STEPS * BATCH);
    double s = 0.0, sq = 0.0;
    for (int i = threadIdx.x; i < T_STEPS * BATCH; i += 256) {
        float v = base[i];
        s += v; sq += (double)v * (double)v;
    }
    __shared__ double rs[256], rq[256];
    rs[threadIdx.x] = s; rq[threadIdx.x] = sq;
    __syncthreads();
    for (int st = 128; st > 0; st >>= 1) {
        if (threadIdx.x < st) { rs[threadIdx.x] += rs[threadIdx.x + st]; rq[threadIdx.x] += rq[threadIdx.x + st]; }
        __syncthreads();
    }
    if (threadIdx.x == 0) {
        double n = (double)(T_STEPS * BATCH);
        double mu = rs[0] / n;
        double var = rq[0] / n - mu * mu;
        float sc = bn_g[c] * (float)(1.0 / sqrt(var + 1e-5));
        g_scale[c] = sc;
        g_shift[c] = bn_b[c] - (float)mu * sc;
    }
}

__global__ void norm_kernel() {
    int i = blockIdx.x * 256 + threadIdx.x;
    if (i >= OC * T_STEPS * BATCH) return;
    int oc = i / (T_STEPS * BATCH);
    int rem = i % (T_STEPS * BATCH);
    int t = rem / BATCH, b = rem % BATCH;
    g_seq[t * (OC * BATCH) + oc * BATCH + b] = g_ybuf[i] * g_scale[oc] + g_shift[oc];
}

// MODE 1: LIF + SLSTM1 (K = 64 spikes + 512 mem1). MODE 2: SLSTM2 (K = 512 spk1 + 512 mem2)
template <int MODE>
__global__ void __launch_bounds__(256) step_kernel(
    int t, const float* __restrict__ w_ih, const float* __restrict__ w_hh,
    const float* __restrict__ b_ih, const float* __restrict__ b_hh,
    const float* __restrict__ thrA_p, const float* __restrict__ thr_p)
{
    __shared__ float s_state[64 * 128];
    __shared__ float s_w[16 * 65];
    __shared__ float s_gates[16 * 128];
    const int tid = threadIdx.x;
    const int h0 = blockIdx.x * 4;
    const int cur = t & 1, nxt = cur ^ 1;
    const float thr = *thr_p;

    const int g = tid & 15;
    const int bbase = (tid >> 4) * 8;
    const int grow = ((g >> 2) * HID) + h0 + (g & 3);

    float rs[32], rw[4];
    ull acc[4] = {0ull, 0ull, 0ull, 0ull};

    // register prefetch of chunk nc
    auto prefetch = [&](int nc) {
        const float* src; const float* wb; int koff;
        if (MODE == 1) { src = g_mem1[cur] + (nc - 1) * 8192; wb = w_hh; koff = (nc - 1) * 64; }
        else {
            src = (nc < 8) ? g_spk1 + nc * 8192 : g_mem2[cur] + (nc - 8) * 8192;
            wb  = (nc < 8) ? w_ih : w_hh;
            koff = (nc & 7) * 64;
        }
#pragma unroll
        for (int j = 0; j < 32; j++) rs[j] = src[tid + j * 256];
#pragma unroll
        for (int j = 0; j < 4; j++) {
            int f = tid * 4 + j; int row = f >> 6, kk = f & 63;
            int gr = ((row >> 2) * HID) + h0 + (row & 3);
            rw[j] = wb[gr * HID + koff + kk];
        }
    };
    auto commit = [&]() {
#pragma unroll
        for (int j = 0; j < 32; j++) s_state[tid + j * 256] = rs[j];
#pragma unroll
        for (int j = 0; j < 4; j++) {
            int f = tid * 4 + j; int row = f >> 6, kk = f & 63;
            s_w[row * 65 + kk] = rw[j];
        }
    };

    if (MODE == 1) {
        const float thrL = *thrA_p;
        // LIF spikes into s_state[c][b]; CTA 0 persists new mem_l
        for (int i = tid; i < 64 * 128; i += 256) {
            float old = g_memL[cur][i];
            float xt = g_seq[t * 8192 + i];
            float reset = (old > thrL) ? thrL : 0.f;
            float mn = 0.9f * old + xt - reset;
            if (blockIdx.x == 0) g_memL[nxt][i] = mn;
            s_state[i] = (mn > thrL) ? 1.f : 0.f;
        }
        // w_ih1 rows (stride 64) direct to smem
        for (int i = tid; i < 16 * 64; i += 256) {
            int row = i >> 6, kk = i & 63;
            int gr = ((row >> 2) * HID) + h0 + (row & 3);
            s_w[row * 65 + kk] = w_ih[gr * 64 + kk];
        }
        prefetch(1);
        __syncthreads();
        gemm64(s_state, s_w, g, bbase, acc);
        for (int ch = 1; ch <= 8; ch++) {
            __syncthreads();
            commit();
            __syncthreads();
            if (ch < 8) prefetch(ch + 1);
            gemm64(s_state, s_w, g, bbase, acc);
        }
    } else {
        prefetch(0);
        for (int ch = 0; ch < 16; ch++) {
            __syncthreads();
            commit();
            __syncthreads();
            if (ch < 15) prefetch(ch + 1);
            gemm64(s_state, s_w, g, bbase, acc);
        }
    }

    float bias = b_ih[grow] + b_hh[grow];
#pragma unroll
    for (int p = 0; p < 4; p++) {
        unsigned lo, hi;
        asm("mov.b64 {%0, %1}, %2;" : "=r"(lo), "=r"(hi) : "l"(acc[p]));
        s_gates[g * 128 + bbase + 2 * p]     = __uint_as_float(lo) + bias;
        s_gates[g * 128 + bbase + 2 * p + 1] = __uint_as_float(hi) + bias;
    }
    __syncthreads();

#pragma unroll
    for (int it = 0; it < 2; it++) {
        int item = tid + it * 256;           // 4 hidden x 128 batch
        int hh = item >> 7, b = item & 127;
        float iv = s_gates[(0  + hh) * 128 + b];
        float fv = s_gates[(4  + hh) * 128 + b];
        float gv = s_gates[(8  + hh) * 128 + b];
        float ov = s_gates[(12 + hh) * 128 + b];
        int idx = (h0 + hh) * 128 + b;
        float syn, memo;
        if (MODE == 1) { syn = g_syn1[idx]; memo = g_mem1[cur][idx]; }
        else           { syn = g_syn2[idx]; memo = g_mem2[cur][idx]; }
        float reset = (memo > thr) ? thr : 0.f;
        float sn = sigf(fv) * syn + sigf(iv) * tanhf(gv);
        float mn = sigf(ov) * tanhf(sn) - reset;
        if (MODE == 1) {
            g_syn1[idx] = sn;
            g_mem1[nxt][idx] = mn;
            g_spk1[idx] = (mn > thr) ? 1.f : 0.f;
        } else {
            g_syn2[idx] = sn;
            g_mem2[nxt][idx] = mn;
            g_acc2[idx] += mn;
        }
    }
}

__global__ void heads_kernel(const float* __restrict__ wg, const float* __restrict__ bg,
                             const float* __restrict__ wd1, const float* __restrict__ bd1,
                             const float* __restrict__ wd2, const float* __restrict__ bd2,
                             const float* __restrict__ thr_dom_p, float* __restrict__ out)
{
    __shared__ float feat[512];
    __shared__ float sd[64];
    int b = blockIdx.x, tid = threadIdx.x;
    const float thr = *thr_dom_p;
#pragma unroll
    for (int j = 0; j < 4; j++)
        feat[tid + j * 128] = g_acc2[(tid + j * 128) * 128 + b] * (1.f / 400.f);
    __syncthreads();
    if (tid < 8) {
        float acc = bg[tid];
        for (int h = 0; h < 512; h++) acc = fmaf(feat[h], wg[tid * 512 + h], acc);
        out[b * 8 + tid] = acc;
    }
    if (tid < 64) {
        float acc = bd1[tid];
        for (int h = 0; h < 512; h++) acc = fmaf(feat[h], wd1[tid * 512 + h], acc);
        sd[tid] = (acc - thr > 0.f) ? 1.f : 0.f;
    }
    __syncthreads();
    if (tid < 10) {
        float acc = bd2[tid];
        for (int k = 0; k < 64; k++) acc = fmaf(sd[k], wd2[tid * 64 + k], acc);
        out[128 * 8 + b * 10 + tid] = acc;
    }
}

extern "C" void kernel_launch(void* const* d_in, const int* in_sizes, int n_in,
                              void* d_out, int out_size) {
    const float* x       = (const float*)d_in[0];
    const float* conv_w  = (const float*)d_in[1];
    const float* bn_g    = (const float*)d_in[2];
    const float* bn_b    = (const float*)d_in[3];
    const float* w_ih1   = (const float*)d_in[4];
    const float* w_hh1   = (const float*)d_in[5];
    const float* b_ih1   = (const float*)d_in[6];
    const float* b_hh1   = (const float*)d_in[7];
    const float* w_ih2   = (const float*)d_in[8];
    const float* w_hh2   = (const float*)d_in[9];
    const float* b_ih2   = (const float*)d_in[10];
    const float* b_hh2   = (const float*)d_in[11];
    const float* wg      = (const float*)d_in[12];
    const float* bg      = (const float*)d_in[13];
    const float* wd1     = (const float*)d_in[14];
    const float* bd1     = (const float*)d_in[15];
    const float* wd2     = (const float*)d_in[16];
    const float* bd2     = (const float*)d_in[17];
    const float* thrL    = (const float*)d_in[18];
    const float* thr1    = (const float*)d_in[19];
    const float* thr2    = (const float*)d_in[20];
    const float* thrD    = (const float*)d_in[21];

    init_kernel<<<512, 256>>>();
    conv_kernel<<<T_STEPS, 128>>>(x, conv_w);
    stats_kernel<<<OC, 256>>>(bn_g, bn_b);
    norm_kernel<<<(OC * T_STEPS * BATCH + 255) / 256, 256>>>();
    for (int t = 0; t < T_STEPS; t++) {
        step_kernel<1><<<128, 256>>>(t, w_ih1, w_hh1, b_ih1, b_hh1, thrL, thr1);
        step_kernel<2><<<128, 256>>>(t, w_ih2, w_hh2, b_ih2, b_hh2, thrL, thr2);
    }
    heads_kernel<<<128, 128>>>(wg, bg, wd1, bd1, wd2, bd2, thrD, (float*)d_out);
}